// round 12
// baseline (speedup 1.0000x reference)
#include <cuda_runtime.h>
#include <cstdint>

#define BB 4
#define LL 2048
#define HH 8
#define EE 64
#define NEG_BIG (-1000.0f)   // ex2(-1000) == 0

// Q pre-scaled by SCALE*log2(e)*(1+2^-11) (K tf32-truncation bias comp).
// Epilogue comp: V truncation (2^-11) * P truncation (2^-12).
#define QSCALE 0.18042493576f
#define BIAS_EPI 1.0007324219f   // (1+2^-11)*(1+2^-12)

#define QTILE 128
#define KTILE 64
#define NTHREADS 256

// smem strides (floats)
#define QP_STR 68   // Q: A-frag loads bank = 4g+q (+8kk) -> conflict-free
#define K_STR  68   // K: B-frag loads bank = 4g+8kk+q   -> conflict-free
#define V_STR  72   // V: B-frag loads bank = 8q+g       -> conflict-free

#define SQP_OFF 0
#define SQP_FLOATS (QTILE * QP_STR)                   // 8704
#define STAGE_K_OFF 0
#define STAGE_V_OFF (KTILE * K_STR)                   // 4352
#define STAGE_FLOATS (KTILE * K_STR + KTILE * V_STR)  // 8960
#define STAGE0_OFF SQP_FLOATS
#define SMEM_FLOATS (SQP_FLOATS + 2 * STAGE_FLOATS)   // 26624
#define SMEM_BYTES  (SMEM_FLOATS * 4)                  // 106496

__device__ __forceinline__ uint32_t to_tf32(float x) {
    uint32_t y;
    asm("cvt.rna.tf32.f32 %0, %1;" : "=r"(y) : "f"(x));
    return y;
}
__device__ __forceinline__ float to_tf32f(float x) {
    return __uint_as_float(to_tf32(x));
}
__device__ __forceinline__ float ex2(float x) {
    float y;
    asm("ex2.approx.f32 %0, %1;" : "=f"(y) : "f"(x));
    return y;
}

__device__ __forceinline__ void mma_tf32(float c[4], const uint32_t a[4],
                                         uint32_t b0, uint32_t b1) {
    asm volatile(
        "mma.sync.aligned.m16n8k8.row.col.f32.tf32.tf32.f32 "
        "{%0,%1,%2,%3}, {%4,%5,%6,%7}, {%8,%9}, {%0,%1,%2,%3};\n"
        : "+f"(c[0]), "+f"(c[1]), "+f"(c[2]), "+f"(c[3])
        : "r"(a[0]), "r"(a[1]), "r"(a[2]), "r"(a[3]), "r"(b0), "r"(b1));
}

__device__ __forceinline__ void cp16(uint32_t smem_dst, const float* gptr) {
    asm volatile("cp.async.cg.shared.global [%0], [%1], 16;\n"
                 :: "r"(smem_dst), "l"(gptr));
}
__device__ __forceinline__ void cp_commit() {
    asm volatile("cp.async.commit_group;\n" ::: "memory");
}
template <int N>
__device__ __forceinline__ void cp_wait() {
    asm volatile("cp.async.wait_group %0;\n" :: "n"(N) : "memory");
}

__global__ __launch_bounds__(NTHREADS, 2)
void sparse_attn_tc7(const float* __restrict__ Q,
                     const float* __restrict__ K,
                     const float* __restrict__ V,
                     float* __restrict__ Out) {
    extern __shared__ float sm[];
    float* sQP = sm + SQP_OFF;   // Q tile: read-only after init (no P aliasing!)

    const int tid  = threadIdx.x;
    const int warp = tid >> 5;    // 0..7
    const int lane = tid & 31;
    const int g    = lane >> 2;
    const int q    = lane & 3;
    const int m0   = warp * 16;   // warp owns local rows m0..m0+15

    const int qt = (int)(gridDim.x - 1u - blockIdx.x);  // heavy tiles first
    const int h  = blockIdx.y;
    const int b  = blockIdx.z;

    const int kt_max = 2 * qt + 1;
    const size_t bh_base = ((size_t)b * LL) * HH + h;   // row stride = HH*EE

    const int s_row = tid >> 4;        // 0..15
    const int s_c4  = tid & 15;        // 16B chunk within the 64-float row

#define STAGE_KV(kt_, s_)                                                        \
    {                                                                            \
        float* stg = sm + STAGE0_OFF + (s_) * STAGE_FLOATS;                      \
        uint32_t kbase = (uint32_t)__cvta_generic_to_shared(                     \
            stg + STAGE_K_OFF + s_c4 * 4);                                       \
        uint32_t vbase = (uint32_t)__cvta_generic_to_shared(                     \
            stg + STAGE_V_OFF + s_c4 * 4);                                       \
        _Pragma("unroll")                                                        \
        for (int i = 0; i < 4; ++i) {                                            \
            int row = s_row + i * 16;                                            \
            const float* kg = K + ((bh_base + ((size_t)(kt_) * KTILE + row) * HH) \
                                   * EE) + s_c4 * 4;                             \
            const float* vg = V + ((bh_base + ((size_t)(kt_) * KTILE + row) * HH) \
                                   * EE) + s_c4 * 4;                             \
            cp16(kbase + (uint32_t)(row * K_STR) * 4u, kg);                      \
            cp16(vbase + (uint32_t)(row * V_STR) * 4u, vg);                      \
        }                                                                        \
        cp_commit();                                                             \
    }

    // ---- prologue: start stages 0 and 1 ----
    STAGE_KV(0, 0)
    STAGE_KV(1, 1)

    // ---- stage Q tile (128x64), coalesced, pre-scaled + tf32-rounded ----
#pragma unroll
    for (int i = 0; i < 8; ++i) {
        int f = tid + i * NTHREADS;
        int row = f >> 4, c4 = f & 15;
        const float4 v = *reinterpret_cast<const float4*>(
            Q + ((bh_base + ((size_t)qt * QTILE + row) * HH) * EE) + c4 * 4);
        float4 cv = make_float4(to_tf32f(v.x * QSCALE), to_tf32f(v.y * QSCALE),
                                to_tf32f(v.z * QSCALE), to_tf32f(v.w * QSCALE));
        *reinterpret_cast<float4*>(sQP + row * QP_STR + c4 * 4) = cv;
    }
    __syncthreads();

    float o[8][4];
#pragma unroll
    for (int t = 0; t < 8; ++t) {
        o[t][0] = 0.f; o[t][1] = 0.f; o[t][2] = 0.f; o[t][3] = 0.f;
    }
    float l_run0 = 0.f, l_run1 = 0.f;   // fixed-shift softmax accumulators

    const int r0g = qt * QTILE + m0 + g;   // global q-row of c0/c1
    const int r1g = r0g + 8;               // global q-row of c2/c3

    // shfl sources for the C->A fragment permutation (GEMM2)
    const int srcA = 4 * g + (q >> 1);      // cols 8kk+q
    const int srcB = srcA + 2;              // cols 8kk+q+4
    const bool odd = (q & 1);

    for (int kt = 0; kt <= kt_max; ++kt) {
        if (kt < kt_max) cp_wait<1>(); else cp_wait<0>();
        __syncthreads();

        float* stg = sm + STAGE0_OFF + (kt & 1) * STAGE_FLOATS;
        float* sK  = stg + STAGE_K_OFF;
        float* sV  = stg + STAGE_V_OFF;

        const bool active = (kt * KTILE <= qt * QTILE + m0 + 15);
        if (active) {
            // ---- GEMM1: S[16x64] = Q * K^T (A-frags reloaded from smem) ----
            float sc[8][4];
#pragma unroll
            for (int t = 0; t < 8; ++t) {
                sc[t][0] = 0.f; sc[t][1] = 0.f; sc[t][2] = 0.f; sc[t][3] = 0.f;
            }
#pragma unroll
            for (int kk = 0; kk < 8; ++kk) {
                uint32_t a[4];
                a[0] = __float_as_uint(sQP[(m0 + g) * QP_STR + 8 * kk + q]);
                a[1] = __float_as_uint(sQP[(m0 + g + 8) * QP_STR + 8 * kk + q]);
                a[2] = __float_as_uint(sQP[(m0 + g) * QP_STR + 8 * kk + q + 4]);
                a[3] = __float_as_uint(sQP[(m0 + g + 8) * QP_STR + 8 * kk + q + 4]);
#pragma unroll
                for (int t = 0; t < 8; ++t) {
                    uint32_t b0 = __float_as_uint(sK[(8 * t + g) * K_STR + 8 * kk + q]);
                    uint32_t b1 = __float_as_uint(sK[(8 * t + g) * K_STR + 8 * kk + q + 4]);
                    mma_tf32(sc[t], a, b0, b1);
                }
            }

            // ---- mask fast-path check (16 rows x 64 cols warp tile) ----
            const int dmin = qt * QTILE + m0 - (kt * KTILE + 63);
            const int dmax = dmin + 78;
            bool hit = false;
            if (dmax >= 2) {
                const int lo = dmin > 2 ? dmin : 2;
                const int hp = 1 << (31 - __clz(dmax));
                hit = hp >= lo;
            }
            const bool need_mask = hit || (dmin < 0);

            const int jb = kt * KTILE + 2 * q;
            float ls0 = 0.f, ls1 = 0.f;
            if (need_mask) {
#pragma unroll
                for (int t = 0; t < 8; ++t) {
                    const int j0 = jb + 8 * t, j1 = j0 + 1;
#pragma unroll
                    for (int e = 0; e < 4; ++e) {
                        const int ig = (e < 2) ? r0g : r1g;
                        const int jg = (e & 1) ? j1 : j0;
                        const int d  = ig - jg;
                        float x = sc[t][e];
                        if (d >= 2 && (d & (d - 1)) == 0) x = 0.0f; // exp->1
                        if (d < 0) x = NEG_BIG;                     // exp->0
                        sc[t][e] = ex2(x);
                    }
                    ls0 += sc[t][0] + sc[t][1];
                    ls1 += sc[t][2] + sc[t][3];
                }
            } else {
#pragma unroll
                for (int t = 0; t < 8; ++t) {
                    sc[t][0] = ex2(sc[t][0]);
                    sc[t][1] = ex2(sc[t][1]);
                    sc[t][2] = ex2(sc[t][2]);
                    sc[t][3] = ex2(sc[t][3]);
                    ls0 += sc[t][0] + sc[t][1];
                    ls1 += sc[t][2] + sc[t][3];
                }
            }
            l_run0 += ls0;
            l_run1 += ls1;

            // ---- GEMM2: O[16x64] += P * V.  P stays in registers: the
            // C-fragment of GEMM1 is permuted into A-fragments via shfl.
            // A[g][8kk+q]   = lane(4g + (q>>1)),  reg c[q&1]   of sc[kk]
            // A[g][8kk+q+4] = lane(4g + (q>>1)+2), reg c[q&1]
#pragma unroll
            for (int kk = 0; kk < 8; ++kk) {
                float x0 = __shfl_sync(0xffffffffu, sc[kk][0], srcA);
                float x1 = __shfl_sync(0xffffffffu, sc[kk][1], srcA);
                float x2 = __shfl_sync(0xffffffffu, sc[kk][2], srcA);
                float x3 = __shfl_sync(0xffffffffu, sc[kk][3], srcA);
                float y0 = __shfl_sync(0xffffffffu, sc[kk][0], srcB);
                float y1 = __shfl_sync(0xffffffffu, sc[kk][1], srcB);
                float y2 = __shfl_sync(0xffffffffu, sc[kk][2], srcB);
                float y3 = __shfl_sync(0xffffffffu, sc[kk][3], srcB);
                uint32_t pa[4];
                pa[0] = __float_as_uint(odd ? x1 : x0);
                pa[1] = __float_as_uint(odd ? x3 : x2);
                pa[2] = __float_as_uint(odd ? y1 : y0);
                pa[3] = __float_as_uint(odd ? y3 : y2);
#pragma unroll
                for (int t = 0; t < 8; ++t) {
                    uint32_t b0 = __float_as_uint(sV[(8 * kk + q) * V_STR + 8 * t + g]);
                    uint32_t b1 = __float_as_uint(sV[(8 * kk + q + 4) * V_STR + 8 * t + g]);
                    mma_tf32(o[t], pa, b0, b1);
                }
            }
        }
        __syncthreads();  // all warps done with stage (kt&1) before refilling it

        if (kt + 2 <= kt_max) {
            STAGE_KV(kt + 2, kt & 1)
        }
    }

    // ---- epilogue: deferred l reduction, normalize (+V,P bias comp), write ----
    float l0 = l_run0, l1 = l_run1;
    l0 += __shfl_xor_sync(0xffffffffu, l0, 1);
    l0 += __shfl_xor_sync(0xffffffffu, l0, 2);
    l1 += __shfl_xor_sync(0xffffffffu, l1, 1);
    l1 += __shfl_xor_sync(0xffffffffu, l1, 2);
    const float inv0 = BIAS_EPI / l0;
    const float inv1 = BIAS_EPI / l1;
#pragma unroll
    for (int t = 0; t < 8; ++t) {
        const int col = 8 * t + 2 * q;
        float2 w0 = make_float2(o[t][0] * inv0, o[t][1] * inv0);
        float2 w1 = make_float2(o[t][2] * inv1, o[t][3] * inv1);
        *reinterpret_cast<float2*>(
            Out + ((bh_base + (size_t)r0g * HH) * EE) + col) = w0;
        *reinterpret_cast<float2*>(
            Out + ((bh_base + (size_t)r1g * HH) * EE) + col) = w1;
    }
}

extern "C" void kernel_launch(void* const* d_in, const int* in_sizes, int n_in,
                              void* d_out, int out_size) {
    const float* Qp = (const float*)d_in[0];
    const float* Kp = (const float*)d_in[1];
    const float* Vp = (const float*)d_in[2];
    float* Op = (float*)d_out;

    cudaFuncSetAttribute(sparse_attn_tc7,
                         cudaFuncAttributeMaxDynamicSharedMemorySize, SMEM_BYTES);

    dim3 grid(LL / QTILE, HH, BB);  // (16, 8, 4)
    sparse_attn_tc7<<<grid, NTHREADS, SMEM_BYTES>>>(Qp, Kp, Vp, Op);
}

// round 14
// speedup vs baseline: 1.5040x; 1.5040x over previous
#include <cuda_runtime.h>
#include <cuda_fp16.h>
#include <cstdint>

#define BB 4
#define LL 2048
#define HH 8
#define EE 64
#define NTHREADS 256
#define NEG_BIG (-1000.0f)          // ex2(-1000) == 0
#define QSCALE 0.18033688011f       // 0.125 * log2(e)  (no bias comp needed: all rn)

#define QTILE 128
#define KTILE 64
#define H_STR 72                    // half stride: 144B rows -> LDSM conflict-free

// ---- smem layout (bytes) ----
#define SQH_OFF 0                         // Q fp16: 128 x 72 halves = 18432
#define SKH_OFF 18432                     // K fp16: 64 x 72 = 9216
#define SVH_OFF 27648                     // V fp16: 64 x 72 = 9216
#define STGF_OFF 36864                    // 2 fp32 stages x 32768 (K 16384 + V 16384)
#define SMEM_BYTES (STGF_OFF + 2 * 32768) // 102400

__device__ __forceinline__ float ex2f(float x) {
    float y; asm("ex2.approx.f32 %0, %1;" : "=f"(y) : "f"(x)); return y;
}
__device__ __forceinline__ uint32_t packh2(float lo, float hi) {
    __half2 h = __floats2half2_rn(lo, hi);
    return *reinterpret_cast<uint32_t*>(&h);
}
__device__ __forceinline__ void mma_f16(float c[4], uint32_t a0, uint32_t a1,
                                        uint32_t a2, uint32_t a3,
                                        uint32_t b0, uint32_t b1) {
    asm volatile(
        "mma.sync.aligned.m16n8k16.row.col.f32.f16.f16.f32 "
        "{%0,%1,%2,%3}, {%4,%5,%6,%7}, {%8,%9}, {%0,%1,%2,%3};\n"
        : "+f"(c[0]), "+f"(c[1]), "+f"(c[2]), "+f"(c[3])
        : "r"(a0), "r"(a1), "r"(a2), "r"(a3), "r"(b0), "r"(b1));
}
#define LDSM4(r0, r1, r2, r3, addr) \
    asm volatile("ldmatrix.sync.aligned.m8n8.x4.shared.b16 {%0,%1,%2,%3}, [%4];" \
                 : "=r"(r0), "=r"(r1), "=r"(r2), "=r"(r3) : "r"(addr))
#define LDSM4T(r0, r1, r2, r3, addr) \
    asm volatile("ldmatrix.sync.aligned.m8n8.x4.trans.shared.b16 {%0,%1,%2,%3}, [%4];" \
                 : "=r"(r0), "=r"(r1), "=r"(r2), "=r"(r3) : "r"(addr))

__device__ __forceinline__ void cp16(uint32_t smem_dst, const float* gptr) {
    asm volatile("cp.async.cg.shared.global [%0], [%1], 16;\n"
                 :: "r"(smem_dst), "l"(gptr));
}
__device__ __forceinline__ void cp_commit() {
    asm volatile("cp.async.commit_group;\n" ::: "memory");
}
template <int N>
__device__ __forceinline__ void cp_wait() {
    asm volatile("cp.async.wait_group %0;\n" :: "n"(N) : "memory");
}

__global__ __launch_bounds__(NTHREADS, 1)
void sparse_attn_f16(const float* __restrict__ Q,
                     const float* __restrict__ K,
                     const float* __restrict__ V,
                     float* __restrict__ Out) {
    extern __shared__ __align__(256) uint8_t smem[];
    __half* sQh = (__half*)(smem + SQH_OFF);
    __half* sKh = (__half*)(smem + SKH_OFF);
    __half* sVh = (__half*)(smem + SVH_OFF);

    uint32_t sb;
    asm("{ .reg .u64 t; cvta.to.shared.u64 t, %1; cvt.u32.u64 %0, t; }"
        : "=r"(sb) : "l"(smem));
    const uint32_t sq_u32  = sb + SQH_OFF;
    const uint32_t sk_u32  = sb + SKH_OFF;
    const uint32_t sv_u32  = sb + SVH_OFF;
    const uint32_t stg_u32 = sb + STGF_OFF;

    const int tid  = threadIdx.x;
    const int warp = tid >> 5;        // 0..7
    const int lane = tid & 31;
    const int g    = lane >> 2;
    const int q    = lane & 3;
    const int m0   = warp * 16;       // warp owns local rows m0..m0+15
    const int l8   = lane & 7;
    const int lb3  = (lane >> 3) & 1;
    const int lb4  = lane >> 4;

    const int qt = (int)(gridDim.x - 1u - blockIdx.x);  // heavy tiles first
    const int h  = blockIdx.y;
    const int b  = blockIdx.z;
    const int kt_max = 2 * qt + 1;
    const size_t bh_base = ((size_t)b * LL) * HH + h;

    const int s_row = tid >> 4;       // 0..15
    const int s_c4  = tid & 15;

#define STAGE_KV(kt_, s_)                                                        \
    {                                                                            \
        uint32_t kb = stg_u32 + (uint32_t)(s_) * 32768u + s_c4 * 16u;            \
        uint32_t vb = kb + 16384u;                                               \
        _Pragma("unroll")                                                        \
        for (int i = 0; i < 4; ++i) {                                            \
            int row = s_row + i * 16;                                            \
            const size_t goff = (bh_base + ((size_t)(kt_) * KTILE + row) * HH)   \
                                * EE + s_c4 * 4;                                 \
            cp16(kb + (uint32_t)row * 256u, K + goff);                           \
            cp16(vb + (uint32_t)row * 256u, V + goff);                           \
        }                                                                        \
        cp_commit();                                                             \
    }

    // ---- prologue: start fp32 stages 0 and 1 ----
    STAGE_KV(0, 0)
    STAGE_KV(1, 1)

    // ---- Q: gmem fp32 -> smem fp16 (prescaled, rn) ----
#pragma unroll
    for (int i = 0; i < 8; ++i) {
        int f = tid + i * NTHREADS;          // float4 index, 0..2047
        int row = f >> 4, c4 = f & 15;
        const float4 v = *reinterpret_cast<const float4*>(
            Q + ((bh_base + ((size_t)qt * QTILE + row) * HH) * EE) + c4 * 4);
        uint32_t u0 = packh2(v.x * QSCALE, v.y * QSCALE);
        uint32_t u1 = packh2(v.z * QSCALE, v.w * QSCALE);
        *reinterpret_cast<uint2*>(sQh + row * H_STR + c4 * 4) = make_uint2(u0, u1);
    }
    __syncthreads();

    float o[8][4];
#pragma unroll
    for (int t = 0; t < 8; ++t) {
        o[t][0] = 0.f; o[t][1] = 0.f; o[t][2] = 0.f; o[t][3] = 0.f;
    }
    float l_run0 = 0.f, l_run1 = 0.f;

    const int r0g = qt * QTILE + m0 + g;
    const int r1g = r0g + 8;

    for (int kt = 0; kt <= kt_max; ++kt) {
        if (kt < kt_max) cp_wait<1>(); else cp_wait<0>();
        __syncthreads();

        // ---- convert fp32 stage (kt&1) -> fp16 K/V tiles ----
        const float4* kf = reinterpret_cast<const float4*>(
            smem + STGF_OFF + (kt & 1) * 32768);
        const float4* vf = kf + 1024;
#pragma unroll
        for (int i = 0; i < 4; ++i) {
            int f = tid + i * NTHREADS;      // 0..1023
            int row = f >> 4, c4 = f & 15;
            float4 kv = kf[f];
            *reinterpret_cast<uint2*>(sKh + row * H_STR + c4 * 4) =
                make_uint2(packh2(kv.x, kv.y), packh2(kv.z, kv.w));
            float4 vv = vf[f];
            *reinterpret_cast<uint2*>(sVh + row * H_STR + c4 * 4) =
                make_uint2(packh2(vv.x, vv.y), packh2(vv.z, vv.w));
        }
        __syncthreads();

        // fp32 stage (kt&1) is now free: refill for kt+2 immediately
        if (kt + 2 <= kt_max) {
            STAGE_KV(kt + 2, kt & 1)
        }

        const bool active = (kt * KTILE <= qt * QTILE + m0 + 15);
        if (active) {
            // ---- GEMM1: S[16x64] = Q * K^T (fp16, ldmatrix fragments) ----
            float sc[8][4];
#pragma unroll
            for (int t = 0; t < 8; ++t) {
                sc[t][0] = 0.f; sc[t][1] = 0.f; sc[t][2] = 0.f; sc[t][3] = 0.f;
            }
#pragma unroll
            for (int kk = 0; kk < 4; ++kk) {
                uint32_t a0, a1, a2, a3;
                LDSM4(a0, a1, a2, a3,
                      sq_u32 + (uint32_t)((m0 + lb3 * 8 + l8) * H_STR
                                          + 16 * kk + lb4 * 8) * 2u);
#pragma unroll
                for (int tp = 0; tp < 4; ++tp) {
                    uint32_t b0, b1, b2, b3;
                    LDSM4(b0, b1, b2, b3,
                          sk_u32 + (uint32_t)((16 * tp + lb4 * 8 + l8) * H_STR
                                              + 16 * kk + lb3 * 8) * 2u);
                    mma_f16(sc[2 * tp],     a0, a1, a2, a3, b0, b1);
                    mma_f16(sc[2 * tp + 1], a0, a1, a2, a3, b2, b3);
                }
            }

            // ---- mask fast-path ----
            const int dmin = qt * QTILE + m0 - (kt * KTILE + 63);
            const int dmax = dmin + 78;
            bool hit = false;
            if (dmax >= 2) {
                const int lo = dmin > 2 ? dmin : 2;
                const int hp = 1 << (31 - __clz(dmax));
                hit = hp >= lo;
            }
            const bool need_mask = hit || (dmin < 0);

            const int jb = kt * KTILE + 2 * q;
            float ls0 = 0.f, ls1 = 0.f;
            if (need_mask) {
#pragma unroll
                for (int t = 0; t < 8; ++t) {
                    const int j0 = jb + 8 * t, j1 = j0 + 1;
#pragma unroll
                    for (int e = 0; e < 4; ++e) {
                        const int ig = (e < 2) ? r0g : r1g;
                        const int jg = (e & 1) ? j1 : j0;
                        const int d  = ig - jg;
                        float x = sc[t][e];
                        if (d >= 2 && (d & (d - 1)) == 0) x = 0.0f;  // exp->1
                        if (d < 0) x = NEG_BIG;                      // exp->0
                        sc[t][e] = ex2f(x);
                    }
                    ls0 += sc[t][0] + sc[t][1];
                    ls1 += sc[t][2] + sc[t][3];
                }
            } else {
#pragma unroll
                for (int t = 0; t < 8; ++t) {
                    sc[t][0] = ex2f(sc[t][0]);
                    sc[t][1] = ex2f(sc[t][1]);
                    sc[t][2] = ex2f(sc[t][2]);
                    sc[t][3] = ex2f(sc[t][3]);
                    ls0 += sc[t][0] + sc[t][1];
                    ls1 += sc[t][2] + sc[t][3];
                }
            }
            l_run0 += ls0;
            l_run1 += ls1;

            // ---- GEMM2: O += P * V.  P's fp16 A-frag = per-lane pack of
            // GEMM1's C-frag: a0=pk(sc[2kk].c0,c1) a1=pk(c2,c3)
            //                 a2=pk(sc[2kk+1].c0,c1) a3=pk(c2,c3). No shfl/smem.
#pragma unroll
            for (int kk = 0; kk < 4; ++kk) {
                uint32_t p0 = packh2(sc[2 * kk][0],     sc[2 * kk][1]);
                uint32_t p1 = packh2(sc[2 * kk][2],     sc[2 * kk][3]);
                uint32_t p2 = packh2(sc[2 * kk + 1][0], sc[2 * kk + 1][1]);
                uint32_t p3 = packh2(sc[2 * kk + 1][2], sc[2 * kk + 1][3]);
#pragma unroll
                for (int tp = 0; tp < 4; ++tp) {
                    uint32_t v0, v1, v2, v3;
                    LDSM4T(v0, v1, v2, v3,
                           sv_u32 + (uint32_t)((16 * kk + lb3 * 8 + l8) * H_STR
                                               + 16 * tp + lb4 * 8) * 2u);
                    mma_f16(o[2 * tp],     p0, p1, p2, p3, v0, v1);
                    mma_f16(o[2 * tp + 1], p0, p1, p2, p3, v2, v3);
                }
            }
        }
        __syncthreads();   // all warps done with sKh/sVh before next conversion
    }

    // ---- epilogue: deferred l reduction, normalize, write ----
    float l0 = l_run0, l1 = l_run1;
    l0 += __shfl_xor_sync(0xffffffffu, l0, 1);
    l0 += __shfl_xor_sync(0xffffffffu, l0, 2);
    l1 += __shfl_xor_sync(0xffffffffu, l1, 1);
    l1 += __shfl_xor_sync(0xffffffffu, l1, 2);
    const float inv0 = 1.0f / l0;
    const float inv1 = 1.0f / l1;
#pragma unroll
    for (int t = 0; t < 8; ++t) {
        const int col = 8 * t + 2 * q;
        float2 w0 = make_float2(o[t][0] * inv0, o[t][1] * inv0);
        float2 w1 = make_float2(o[t][2] * inv1, o[t][3] * inv1);
        *reinterpret_cast<float2*>(
            Out + ((bh_base + (size_t)r0g * HH) * EE) + col) = w0;
        *reinterpret_cast<float2*>(
            Out + ((bh_base + (size_t)r1g * HH) * EE) + col) = w1;
    }
}

extern "C" void kernel_launch(void* const* d_in, const int* in_sizes, int n_in,
                              void* d_out, int out_size) {
    const float* Qp = (const float*)d_in[0];
    const float* Kp = (const float*)d_in[1];
    const float* Vp = (const float*)d_in[2];
    float* Op = (float*)d_out;

    cudaFuncSetAttribute(sparse_attn_f16,
                         cudaFuncAttributeMaxDynamicSharedMemorySize, SMEM_BYTES);

    dim3 grid(LL / QTILE, HH, BB);  // (16, 8, 4)
    sparse_attn_f16<<<grid, NTHREADS, SMEM_BYTES>>>(Qp, Kp, Vp, Op);
}

// round 15
// speedup vs baseline: 1.8043x; 1.1997x over previous
#include <cuda_runtime.h>
#include <cuda_fp16.h>
#include <cstdint>

#define BB 4
#define LL 2048
#define HH 8
#define EE 64
#define NTHREADS 256
#define NEG_BIG (-1000.0f)
#define QSCALE 0.18033688011f       // 0.125 * log2(e)

#define QTILE 128
#define KTILE 64
#define H_STR 72                    // fp16 stride: 144B rows -> LDSM conflict-free
#define NELEM (BB * LL * HH * EE)   // 4,194,304

// fp16 scratch (device-global: the sanctioned scratch mechanism)
__device__ __half d_Qh[NELEM];
__device__ __half d_Kh[NELEM];
__device__ __half d_Vh[NELEM];

// ---- smem layout (bytes): Q slab + 3 fp16 stages ----
#define SQH_OFF 0                          // 128 x 72 halves = 18432
#define STG_OFF 18432                      // 3 stages x (K 9216 + V 9216)
#define STG_BYTES 18432
#define STG_V 9216
#define SMEM_BYTES (STG_OFF + 3 * STG_BYTES)   // 73728

__device__ __forceinline__ float ex2f(float x) {
    float y; asm("ex2.approx.f32 %0, %1;" : "=f"(y) : "f"(x)); return y;
}
__device__ __forceinline__ uint32_t packh2(float lo, float hi) {
    __half2 h = __floats2half2_rn(lo, hi);
    return *reinterpret_cast<uint32_t*>(&h);
}
__device__ __forceinline__ void mma_f16(float c[4], uint32_t a0, uint32_t a1,
                                        uint32_t a2, uint32_t a3,
                                        uint32_t b0, uint32_t b1) {
    asm volatile(
        "mma.sync.aligned.m16n8k16.row.col.f32.f16.f16.f32 "
        "{%0,%1,%2,%3}, {%4,%5,%6,%7}, {%8,%9}, {%0,%1,%2,%3};\n"
        : "+f"(c[0]), "+f"(c[1]), "+f"(c[2]), "+f"(c[3])
        : "r"(a0), "r"(a1), "r"(a2), "r"(a3), "r"(b0), "r"(b1));
}
#define LDSM4(r0, r1, r2, r3, addr) \
    asm volatile("ldmatrix.sync.aligned.m8n8.x4.shared.b16 {%0,%1,%2,%3}, [%4];" \
                 : "=r"(r0), "=r"(r1), "=r"(r2), "=r"(r3) : "r"(addr))
#define LDSM4T(r0, r1, r2, r3, addr) \
    asm volatile("ldmatrix.sync.aligned.m8n8.x4.trans.shared.b16 {%0,%1,%2,%3}, [%4];" \
                 : "=r"(r0), "=r"(r1), "=r"(r2), "=r"(r3) : "r"(addr))

__device__ __forceinline__ void cp16(uint32_t smem_dst, const void* gptr) {
    asm volatile("cp.async.cg.shared.global [%0], [%1], 16;\n"
                 :: "r"(smem_dst), "l"(gptr));
}
__device__ __forceinline__ void cp_commit() {
    asm volatile("cp.async.commit_group;\n" ::: "memory");
}
template <int N>
__device__ __forceinline__ void cp_wait() {
    asm volatile("cp.async.wait_group %0;\n" :: "n"(N) : "memory");
}

// ---- pre-pass: fp32 -> fp16 (Q prescaled) ----
__global__ __launch_bounds__(256)
void convert_f16(const float* __restrict__ Q, const float* __restrict__ K,
                 const float* __restrict__ V) {
    const int i = blockIdx.x * 256 + threadIdx.x;   // float4 index
    const float4 qv = reinterpret_cast<const float4*>(Q)[i];
    const float4 kv = reinterpret_cast<const float4*>(K)[i];
    const float4 vv = reinterpret_cast<const float4*>(V)[i];
    reinterpret_cast<uint2*>(d_Qh)[i] =
        make_uint2(packh2(qv.x * QSCALE, qv.y * QSCALE),
                   packh2(qv.z * QSCALE, qv.w * QSCALE));
    reinterpret_cast<uint2*>(d_Kh)[i] =
        make_uint2(packh2(kv.x, kv.y), packh2(kv.z, kv.w));
    reinterpret_cast<uint2*>(d_Vh)[i] =
        make_uint2(packh2(vv.x, vv.y), packh2(vv.z, vv.w));
}

__global__ __launch_bounds__(NTHREADS, 2)
void sparse_attn_f16b(float* __restrict__ Out) {
    extern __shared__ __align__(256) uint8_t smem[];
    uint32_t sb;
    asm("{ .reg .u64 t; cvta.to.shared.u64 t, %1; cvt.u32.u64 %0, t; }"
        : "=r"(sb) : "l"(smem));
    const uint32_t sq_u32  = sb + SQH_OFF;
    const uint32_t stg_u32 = sb + STG_OFF;

    const int tid  = threadIdx.x;
    const int warp = tid >> 5;        // 0..7
    const int lane = tid & 31;
    const int g    = lane >> 2;
    const int q    = lane & 3;
    const int m0   = warp * 16;
    const int l8   = lane & 7;
    const int lb3  = (lane >> 3) & 1;
    const int lb4  = lane >> 4;

    const int qt = (int)(gridDim.x - 1u - blockIdx.x);  // heavy tiles first
    const int h  = blockIdx.y;
    const int b  = blockIdx.z;
    const int kt_max = 2 * qt + 1;
    const size_t bh_base = ((size_t)b * LL) * HH + h;   // units of EE halves/floats

    // staging: fp16 rows of 128B = 8 chunks of 16B; chunk c -> row c>>3, ch c&7
#define STAGE_KV(kt_, s_)                                                       \
    {                                                                           \
        uint32_t kb = stg_u32 + (uint32_t)(s_) * STG_BYTES;                     \
        _Pragma("unroll")                                                       \
        for (int i = 0; i < 2; ++i) {                                           \
            int c = tid + i * NTHREADS;      /* 0..511 */                       \
            int row = c >> 3, ch = c & 7;                                       \
            size_t goff = (bh_base + ((size_t)(kt_) * KTILE + row) * HH) * EE   \
                          + ch * 8;                                             \
            uint32_t doff = (uint32_t)(row * 144 + ch * 16);                    \
            cp16(kb + doff, d_Kh + goff);                                       \
            cp16(kb + STG_V + doff, d_Vh + goff);                               \
        }                                                                       \
        cp_commit();                                                            \
    }

    // ---- prologue: Q + stage0 share commit group 0; then stages 1, 2 ----
    {
#pragma unroll
        for (int i = 0; i < 4; ++i) {
            int c = tid + i * NTHREADS;      // 0..1023
            int row = c >> 3, ch = c & 7;
            size_t goff = (bh_base + ((size_t)qt * QTILE + row) * HH) * EE + ch * 8;
            cp16(sq_u32 + (uint32_t)(row * 144 + ch * 16), d_Qh + goff);
        }
        // stage 0 (same group as Q)
        uint32_t kb = stg_u32;
#pragma unroll
        for (int i = 0; i < 2; ++i) {
            int c = tid + i * NTHREADS;
            int row = c >> 3, ch = c & 7;
            size_t goff = (bh_base + ((size_t)row) * HH) * EE + ch * 8;
            uint32_t doff = (uint32_t)(row * 144 + ch * 16);
            cp16(kb + doff, d_Kh + goff);
            cp16(kb + STG_V + doff, d_Vh + goff);
        }
        cp_commit();
    }
    STAGE_KV(1, 1)
    if (2 <= kt_max) { STAGE_KV(2, 2) }

    float o[8][4];
#pragma unroll
    for (int t = 0; t < 8; ++t) {
        o[t][0] = 0.f; o[t][1] = 0.f; o[t][2] = 0.f; o[t][3] = 0.f;
    }
    float l_run0 = 0.f, l_run1 = 0.f;

    const int r0g = qt * QTILE + m0 + g;
    const int r1g = r0g + 8;

    for (int kt = 0; kt <= kt_max; ++kt) {
        // stage kt ready when <= (#groups newer than kt) outstanding
        if (kt + 2 <= kt_max)      cp_wait<2>();
        else if (kt + 1 <= kt_max) cp_wait<1>();
        else                       cp_wait<0>();
        __syncthreads();

        const uint32_t skh = stg_u32 + (uint32_t)(kt % 3) * STG_BYTES;
        const uint32_t svh = skh + STG_V;

        const bool active = (kt * KTILE <= qt * QTILE + m0 + 15);
        if (active) {
            // ---- GEMM1: S[16x64] = Q * K^T ----
            float sc[8][4];
#pragma unroll
            for (int t = 0; t < 8; ++t) {
                sc[t][0] = 0.f; sc[t][1] = 0.f; sc[t][2] = 0.f; sc[t][3] = 0.f;
            }
#pragma unroll
            for (int kk = 0; kk < 4; ++kk) {
                uint32_t a0, a1, a2, a3;
                LDSM4(a0, a1, a2, a3,
                      sq_u32 + (uint32_t)((m0 + lb3 * 8 + l8) * H_STR
                                          + 16 * kk + lb4 * 8) * 2u);
#pragma unroll
                for (int tp = 0; tp < 4; ++tp) {
                    uint32_t b0, b1, b2, b3;
                    LDSM4(b0, b1, b2, b3,
                          skh + (uint32_t)((16 * tp + lb4 * 8 + l8) * H_STR
                                           + 16 * kk + lb3 * 8) * 2u);
                    mma_f16(sc[2 * tp],     a0, a1, a2, a3, b0, b1);
                    mma_f16(sc[2 * tp + 1], a0, a1, a2, a3, b2, b3);
                }
            }

            // ---- mask fast-path ----
            const int dmin = qt * QTILE + m0 - (kt * KTILE + 63);
            const int dmax = dmin + 78;
            bool hit = false;
            if (dmax >= 2) {
                const int lo = dmin > 2 ? dmin : 2;
                const int hp = 1 << (31 - __clz(dmax));
                hit = hp >= lo;
            }
            const bool need_mask = hit || (dmin < 0);

            const int jb = kt * KTILE + 2 * q;
            float ls0 = 0.f, ls1 = 0.f;
            if (need_mask) {
#pragma unroll
                for (int t = 0; t < 8; ++t) {
                    const int j0 = jb + 8 * t, j1 = j0 + 1;
#pragma unroll
                    for (int e = 0; e < 4; ++e) {
                        const int ig = (e < 2) ? r0g : r1g;
                        const int jg = (e & 1) ? j1 : j0;
                        const int d  = ig - jg;
                        float x = sc[t][e];
                        if (d >= 2 && (d & (d - 1)) == 0) x = 0.0f;  // exp->1
                        if (d < 0) x = NEG_BIG;                      // exp->0
                        sc[t][e] = ex2f(x);
                    }
                    ls0 += sc[t][0] + sc[t][1];
                    ls1 += sc[t][2] + sc[t][3];
                }
            } else {
#pragma unroll
                for (int t = 0; t < 8; ++t) {
                    sc[t][0] = ex2f(sc[t][0]);
                    sc[t][1] = ex2f(sc[t][1]);
                    sc[t][2] = ex2f(sc[t][2]);
                    sc[t][3] = ex2f(sc[t][3]);
                    ls0 += sc[t][0] + sc[t][1];
                    ls1 += sc[t][2] + sc[t][3];
                }
            }
            l_run0 += ls0;
            l_run1 += ls1;

            // ---- GEMM2: O += P * V (P = per-lane rn-pack of GEMM1 C-frag) ----
#pragma unroll
            for (int kk = 0; kk < 4; ++kk) {
                uint32_t p0 = packh2(sc[2 * kk][0],     sc[2 * kk][1]);
                uint32_t p1 = packh2(sc[2 * kk][2],     sc[2 * kk][3]);
                uint32_t p2 = packh2(sc[2 * kk + 1][0], sc[2 * kk + 1][1]);
                uint32_t p3 = packh2(sc[2 * kk + 1][2], sc[2 * kk + 1][3]);
#pragma unroll
                for (int tp = 0; tp < 4; ++tp) {
                    uint32_t v0, v1, v2, v3;
                    LDSM4T(v0, v1, v2, v3,
                           svh + (uint32_t)((16 * kk + lb3 * 8 + l8) * H_STR
                                            + 16 * tp + lb4 * 8) * 2u);
                    mma_f16(o[2 * tp],     p0, p1, p2, p3, v0, v1);
                    mma_f16(o[2 * tp + 1], p0, p1, p2, p3, v2, v3);
                }
            }
        }
        __syncthreads();   // all warps done with stage kt%3 before it refills

        if (kt + 3 <= kt_max) {
            STAGE_KV(kt + 3, kt % 3)
        }
    }

    // ---- epilogue: deferred l reduction, normalize, write ----
    float l0 = l_run0, l1 = l_run1;
    l0 += __shfl_xor_sync(0xffffffffu, l0, 1);
    l0 += __shfl_xor_sync(0xffffffffu, l0, 2);
    l1 += __shfl_xor_sync(0xffffffffu, l1, 1);
    l1 += __shfl_xor_sync(0xffffffffu, l1, 2);
    const float inv0 = 1.0f / l0;
    const float inv1 = 1.0f / l1;
#pragma unroll
    for (int t = 0; t < 8; ++t) {
        const int col = 8 * t + 2 * q;
        float2 w0 = make_float2(o[t][0] * inv0, o[t][1] * inv0);
        float2 w1 = make_float2(o[t][2] * inv1, o[t][3] * inv1);
        *reinterpret_cast<float2*>(
            Out + ((bh_base + (size_t)r0g * HH) * EE) + col) = w0;
        *reinterpret_cast<float2*>(
            Out + ((bh_base + (size_t)r1g * HH) * EE) + col) = w1;
    }
}

extern "C" void kernel_launch(void* const* d_in, const int* in_sizes, int n_in,
                              void* d_out, int out_size) {
    const float* Qp = (const float*)d_in[0];
    const float* Kp = (const float*)d_in[1];
    const float* Vp = (const float*)d_in[2];
    float* Op = (float*)d_out;

    convert_f16<<<NELEM / 4 / 256, 256>>>(Qp, Kp, Vp);

    cudaFuncSetAttribute(sparse_attn_f16b,
                         cudaFuncAttributeMaxDynamicSharedMemorySize, SMEM_BYTES);
    dim3 grid(LL / QTILE, HH, BB);  // (16, 8, 4)
    sparse_attn_f16b<<<grid, NTHREADS, SMEM_BYTES>>>(Op);
}

// round 17
// speedup vs baseline: 1.8740x; 1.0386x over previous
#include <cuda_runtime.h>
#include <cuda_fp16.h>
#include <cstdint>

#define BB 4
#define LL 2048
#define HH 8
#define EE 64
#define NTHREADS 256
#define NEG_BIG (-1000.0f)
#define QSCALE 0.18033688011f       // 0.125 * log2(e)

#define QTILE 128
#define KTILE 64
#define H_STR 72                    // fp16 stride: 144B rows -> LDSM conflict-free
#define NELEM (BB * LL * HH * EE)   // 4,194,304

// fp16 scratch (device-global: the sanctioned scratch mechanism)
__device__ __half d_Kh[NELEM];
__device__ __half d_Vh[NELEM];

// ---- smem layout (bytes): Q slab + 4 fp16 stages ----
#define SQH_OFF 0                          // 128 x 72 halves = 18432
#define STG_OFF 18432
#define STG_BYTES 18432                    // K 9216 + V 9216
#define STG_V 9216
#define SMEM_BYTES (STG_OFF + 4 * STG_BYTES)   // 92160

__device__ __forceinline__ float ex2f(float x) {
    float y; asm("ex2.approx.f32 %0, %1;" : "=f"(y) : "f"(x)); return y;
}
__device__ __forceinline__ uint32_t packh2(float lo, float hi) {
    __half2 h = __floats2half2_rn(lo, hi);
    return *reinterpret_cast<uint32_t*>(&h);
}
__device__ __forceinline__ void mma_f16(float c[4], uint32_t a0, uint32_t a1,
                                        uint32_t a2, uint32_t a3,
                                        uint32_t b0, uint32_t b1) {
    asm volatile(
        "mma.sync.aligned.m16n8k16.row.col.f32.f16.f16.f32 "
        "{%0,%1,%2,%3}, {%4,%5,%6,%7}, {%8,%9}, {%0,%1,%2,%3};\n"
        : "+f"(c[0]), "+f"(c[1]), "+f"(c[2]), "+f"(c[3])
        : "r"(a0), "r"(a1), "r"(a2), "r"(a3), "r"(b0), "r"(b1));
}
#define LDSM4(r0, r1, r2, r3, addr) \
    asm volatile("ldmatrix.sync.aligned.m8n8.x4.shared.b16 {%0,%1,%2,%3}, [%4];" \
                 : "=r"(r0), "=r"(r1), "=r"(r2), "=r"(r3) : "r"(addr))
#define LDSM4T(r0, r1, r2, r3, addr) \
    asm volatile("ldmatrix.sync.aligned.m8n8.x4.trans.shared.b16 {%0,%1,%2,%3}, [%4];" \
                 : "=r"(r0), "=r"(r1), "=r"(r2), "=r"(r3) : "r"(addr))

__device__ __forceinline__ void cp16(uint32_t smem_dst, const void* gptr) {
    asm volatile("cp.async.cg.shared.global [%0], [%1], 16;\n"
                 :: "r"(smem_dst), "l"(gptr));
}
__device__ __forceinline__ void cp_commit() {
    asm volatile("cp.async.commit_group;\n" ::: "memory");
}
template <int N>
__device__ __forceinline__ void cp_wait() {
    asm volatile("cp.async.wait_group %0;\n" :: "n"(N) : "memory");
}

// ---- pre-pass: K/V fp32 -> fp16 (Q handled in-kernel) ----
__global__ __launch_bounds__(256)
void convert_kv(const float* __restrict__ K, const float* __restrict__ V) {
    const int i = blockIdx.x * 256 + threadIdx.x;   // float4 index
    const float4 kv = reinterpret_cast<const float4*>(K)[i];
    const float4 vv = reinterpret_cast<const float4*>(V)[i];
    reinterpret_cast<uint2*>(d_Kh)[i] =
        make_uint2(packh2(kv.x, kv.y), packh2(kv.z, kv.w));
    reinterpret_cast<uint2*>(d_Vh)[i] =
        make_uint2(packh2(vv.x, vv.y), packh2(vv.z, vv.w));
}

__global__ __launch_bounds__(NTHREADS, 2)
void sparse_attn_f16c(const float* __restrict__ Q, float* __restrict__ Out) {
    extern __shared__ __align__(256) uint8_t smem[];
    __half* sQh = (__half*)(smem + SQH_OFF);
    uint32_t sb;
    asm("{ .reg .u64 t; cvta.to.shared.u64 t, %1; cvt.u32.u64 %0, t; }"
        : "=r"(sb) : "l"(smem));
    const uint32_t sq_u32  = sb + SQH_OFF;
    const uint32_t stg_u32 = sb + STG_OFF;

    const int tid  = threadIdx.x;
    const int warp = tid >> 5;        // 0..7
    const int lane = tid & 31;
    const int g    = lane >> 2;
    const int q    = lane & 3;
    const int m0   = warp * 16;
    const int l8   = lane & 7;
    const int lb3  = (lane >> 3) & 1;
    const int lb4  = lane >> 4;

    const int qt = (int)(gridDim.x - 1u - blockIdx.x);  // heavy tiles first
    const int h  = blockIdx.y;
    const int b  = blockIdx.z;
    const int kt_max = 2 * qt + 1;
    const size_t bh_base = ((size_t)b * LL) * HH + h;

    // staging: fp16 rows of 128B = 8 chunks of 16B; chunk c -> row c>>3, ch c&7
#define STAGE_KV(kt_, s_)                                                       \
    {                                                                           \
        uint32_t kb = stg_u32 + (uint32_t)(s_) * STG_BYTES;                     \
        _Pragma("unroll")                                                       \
        for (int i = 0; i < 2; ++i) {                                           \
            int c = tid + i * NTHREADS;      /* 0..511 */                       \
            int row = c >> 3, ch = c & 7;                                       \
            size_t goff = (bh_base + ((size_t)(kt_) * KTILE + row) * HH) * EE   \
                          + ch * 8;                                             \
            uint32_t doff = (uint32_t)(row * 144 + ch * 16);                    \
            cp16(kb + doff, d_Kh + goff);                                       \
            cp16(kb + STG_V + doff, d_Vh + goff);                               \
        }                                                                       \
        cp_commit();                                                            \
    }

    // ---- prologue: stages 0..2 via cp.async; Q converted inline (LDG+STS) ----
    STAGE_KV(0, 0)
    if (1 <= kt_max) { STAGE_KV(1, 1) }
    if (2 <= kt_max) { STAGE_KV(2, 2) }

#pragma unroll
    for (int i = 0; i < 8; ++i) {
        int f = tid + i * NTHREADS;          // float4 index 0..2047
        int row = f >> 4, c4 = f & 15;
        const float4 v = *reinterpret_cast<const float4*>(
            Q + ((bh_base + ((size_t)qt * QTILE + row) * HH) * EE) + c4 * 4);
        *reinterpret_cast<uint2*>(sQh + row * H_STR + c4 * 4) =
            make_uint2(packh2(v.x * QSCALE, v.y * QSCALE),
                       packh2(v.z * QSCALE, v.w * QSCALE));
    }

    float o[8][4];
#pragma unroll
    for (int t = 0; t < 8; ++t) {
        o[t][0] = 0.f; o[t][1] = 0.f; o[t][2] = 0.f; o[t][3] = 0.f;
    }
    float l_run0 = 0.f, l_run1 = 0.f;

    const int r0g = qt * QTILE + m0 + g;
    const int r1g = r0g + 8;

    for (int kt = 0; kt <= kt_max; ++kt) {
        // stage kt ready when <= (#groups newer than kt) outstanding
        if (kt + 2 <= kt_max)      cp_wait<2>();
        else if (kt + 1 <= kt_max) cp_wait<1>();
        else                       cp_wait<0>();
        __syncthreads();   // all warps in iteration kt; stage (kt-1)%4 is free

        // refill the stage consumed last iteration for kt+3 (deep prefetch)
        if (kt + 3 <= kt_max) {
            STAGE_KV(kt + 3, (kt + 3) & 3)
        }

        const uint32_t skh = stg_u32 + (uint32_t)(kt & 3) * STG_BYTES;
        const uint32_t svh = skh + STG_V;

        const bool active = (kt * KTILE <= qt * QTILE + m0 + 15);
        if (active) {
            // ---- GEMM1: S[16x64] = Q * K^T ----
            float sc[8][4];
#pragma unroll
            for (int t = 0; t < 8; ++t) {
                sc[t][0] = 0.f; sc[t][1] = 0.f; sc[t][2] = 0.f; sc[t][3] = 0.f;
            }
#pragma unroll
            for (int kk = 0; kk < 4; ++kk) {
                uint32_t a0, a1, a2, a3;
                LDSM4(a0, a1, a2, a3,
                      sq_u32 + (uint32_t)((m0 + lb3 * 8 + l8) * H_STR
                                          + 16 * kk + lb4 * 8) * 2u);
#pragma unroll
                for (int tp = 0; tp < 4; ++tp) {
                    uint32_t b0, b1, b2, b3;
                    LDSM4(b0, b1, b2, b3,
                          skh + (uint32_t)((16 * tp + lb4 * 8 + l8) * H_STR
                                           + 16 * kk + lb3 * 8) * 2u);
                    mma_f16(sc[2 * tp],     a0, a1, a2, a3, b0, b1);
                    mma_f16(sc[2 * tp + 1], a0, a1, a2, a3, b2, b3);
                }
            }

            // ---- mask fast-path ----
            const int dmin = qt * QTILE + m0 - (kt * KTILE + 63);
            const int dmax = dmin + 78;
            bool hit = false;
            if (dmax >= 2) {
                const int lo = dmin > 2 ? dmin : 2;
                const int hp = 1 << (31 - __clz(dmax));
                hit = hp >= lo;
            }
            const bool need_mask = hit || (dmin < 0);

            const int jb = kt * KTILE + 2 * q;
            float ls0 = 0.f, ls1 = 0.f;
            if (need_mask) {
#pragma unroll
                for (int t = 0; t < 8; ++t) {
                    const int j0 = jb + 8 * t, j1 = j0 + 1;
#pragma unroll
                    for (int e = 0; e < 4; ++e) {
                        const int ig = (e < 2) ? r0g : r1g;
                        const int jg = (e & 1) ? j1 : j0;
                        const int d  = ig - jg;
                        float x = sc[t][e];
                        if (d >= 2 && (d & (d - 1)) == 0) x = 0.0f;  // exp->1
                        if (d < 0) x = NEG_BIG;                      // exp->0
                        sc[t][e] = ex2f(x);
                    }
                    ls0 += sc[t][0] + sc[t][1];
                    ls1 += sc[t][2] + sc[t][3];
                }
            } else {
#pragma unroll
                for (int t = 0; t < 8; ++t) {
                    sc[t][0] = ex2f(sc[t][0]);
                    sc[t][1] = ex2f(sc[t][1]);
                    sc[t][2] = ex2f(sc[t][2]);
                    sc[t][3] = ex2f(sc[t][3]);
                    ls0 += sc[t][0] + sc[t][1];
                    ls1 += sc[t][2] + sc[t][3];
                }
            }
            l_run0 += ls0;
            l_run1 += ls1;

            // ---- GEMM2: O += P * V (P = per-lane rn-pack of GEMM1 C-frag) ----
#pragma unroll
            for (int kk = 0; kk < 4; ++kk) {
                uint32_t p0 = packh2(sc[2 * kk][0],     sc[2 * kk][1]);
                uint32_t p1 = packh2(sc[2 * kk][2],     sc[2 * kk][3]);
                uint32_t p2 = packh2(sc[2 * kk + 1][0], sc[2 * kk + 1][1]);
                uint32_t p3 = packh2(sc[2 * kk + 1][2], sc[2 * kk + 1][3]);
#pragma unroll
                for (int tp = 0; tp < 4; ++tp) {
                    uint32_t v0, v1, v2, v3;
                    LDSM4T(v0, v1, v2, v3,
                           svh + (uint32_t)((16 * kk + lb3 * 8 + l8) * H_STR
                                            + 16 * tp + lb4 * 8) * 2u);
                    mma_f16(o[2 * tp],     p0, p1, p2, p3, v0, v1);
                    mma_f16(o[2 * tp + 1], p0, p1, p2, p3, v2, v3);
                }
            }
        }
        // no end-of-iteration barrier: the next iteration's entry barrier
        // is what licenses the refill of the stage consumed here.
    }

    // ---- epilogue: deferred l reduction, normalize, write ----
    float l0 = l_run0, l1 = l_run1;
    l0 += __shfl_xor_sync(0xffffffffu, l0, 1);
    l0 += __shfl_xor_sync(0xffffffffu, l0, 2);
    l1 += __shfl_xor_sync(0xffffffffu, l1, 1);
    l1 += __shfl_xor_sync(0xffffffffu, l1, 2);
    const float inv0 = 1.0f / l0;
    const float inv1 = 1.0f / l1;
#pragma unroll
    for (int t = 0; t < 8; ++t) {
        const int col = 8 * t + 2 * q;
        float2 w0 = make_float2(o[t][0] * inv0, o[t][1] * inv0);
        float2 w1 = make_float2(o[t][2] * inv1, o[t][3] * inv1);
        *reinterpret_cast<float2*>(
            Out + ((bh_base + (size_t)r0g * HH) * EE) + col) = w0;
        *reinterpret_cast<float2*>(
            Out + ((bh_base + (size_t)r1g * HH) * EE) + col) = w1;
    }
}

extern "C" void kernel_launch(void* const* d_in, const int* in_sizes, int n_in,
                              void* d_out, int out_size) {
    const float* Qp = (const float*)d_in[0];
    const float* Kp = (const float*)d_in[1];
    const float* Vp = (const float*)d_in[2];
    float* Op = (float*)d_out;

    convert_kv<<<NELEM / 4 / 256, 256>>>(Kp, Vp);

    cudaFuncSetAttribute(sparse_attn_f16c,
                         cudaFuncAttributeMaxDynamicSharedMemorySize, SMEM_BYTES);
    dim3 grid(LL / QTILE, HH, BB);  // (16, 8, 4)
    sparse_attn_f16c<<<grid, NTHREADS, SMEM_BYTES>>>(Qp, Op);
}